// round 11
// baseline (speedup 1.0000x reference)
#include <cuda_runtime.h>
#include <cuda_fp16.h>
#include <cstdint>

// Problem dims (fixed by the dataset)
#define B_DIM 8192
#define DIN   1024
#define H_DIM 2048

// Tiling: 128x128 CTA tile, 8 warps (warp tile 64x32), 2 CTAs per SM
#define BM 128
#define BN 128
#define BKE 64          // fp16 K-elements per chunk = 128B rows (swizzle atom)
#define NK 48           // 3072 / 64
#define NKX 16          // first 16 chunks: x / win (K=1024)
#define STAGES 3
#define NTHREADS 256    // 8 warps, warp tile 64x32

#define A_BYTES (BM * 128)                 // 16 KB
#define B_BYTES (BN * 128)                 // 16 KB
#define STAGE_BYTES (A_BYTES + B_BYTES)    // 32 KB
#define SMEM_TOTAL (STAGES * STAGE_BYTES)  // 96 KB  (x2 CTAs = 192 KB/SM)

// fp16 copies of the inputs (static scratch; no allocation allowed)
__device__ __half g_xh[(size_t)B_DIM * DIN];
__device__ __half g_uh[(size_t)B_DIM * H_DIM];
__device__ __half g_winh[(size_t)H_DIM * DIN];
__device__ __half g_wrh[(size_t)H_DIM * H_DIM];

__device__ __forceinline__ uint32_t smem_u32(const void* p) {
    uint32_t a;
    asm("{ .reg .u64 t; cvta.to.shared.u64 t, %1; cvt.u32.u64 %0, t; }"
        : "=r"(a) : "l"(p));
    return a;
}

__device__ __forceinline__ void cp_async16(uint32_t saddr, const void* g) {
    asm volatile("cp.async.cg.shared.global [%0], [%1], 16;\n"
                 :: "r"(saddr), "l"(g));
}

__device__ __forceinline__ void cp_commit() {
    asm volatile("cp.async.commit_group;\n" ::: "memory");
}

template <int N>
__device__ __forceinline__ void cp_wait() {
    asm volatile("cp.async.wait_group %0;\n" :: "n"(N) : "memory");
}

#define LDSM_X4(r, addr) \
    asm volatile("ldmatrix.sync.aligned.m8n8.x4.shared.b16 {%0,%1,%2,%3}, [%4];" \
        : "=r"((r)[0]), "=r"((r)[1]), "=r"((r)[2]), "=r"((r)[3]) : "r"(addr))

// fp16-accumulator MMA: D(f16x2 x2) = A(f16) * B(f16) + C(f16)
__device__ __forceinline__ void mma_f16(uint32_t* c, const uint32_t* a,
                                        uint32_t b0, uint32_t b1) {
    asm volatile(
        "mma.sync.aligned.m16n8k16.row.col.f16.f16.f16.f16 "
        "{%0,%1}, {%2,%3,%4,%5}, {%6,%7}, {%0,%1};"
        : "+r"(c[0]), "+r"(c[1])
        : "r"(a[0]), "r"(a[1]), "r"(a[2]), "r"(a[3]), "r"(b0), "r"(b1));
}

// ---------------------------------------------------------------------------
// fp32 -> fp16 conversion pre-pass (one float4 per thread)
// ---------------------------------------------------------------------------
#define SX4 ((size_t)B_DIM * DIN / 4)     // 2,097,152
#define SU4 ((size_t)B_DIM * H_DIM / 4)   // 4,194,304
#define SW4 ((size_t)H_DIM * DIN / 4)     //   524,288
#define SR4 ((size_t)H_DIM * H_DIM / 4)   // 1,048,576
#define TOTAL4 (SX4 + SU4 + SW4 + SR4)    // 7,864,320

__global__ void __launch_bounds__(256)
convert_kernel(const float4* __restrict__ x, const float4* __restrict__ u,
               const float4* __restrict__ win, const float4* __restrict__ wr) {
    const size_t i = (size_t)blockIdx.x * blockDim.x + threadIdx.x;
    float4 f;
    __half* dst;
    size_t j;
    if (i < SX4)                   { j = i;                   f = x[j];   dst = g_xh;   }
    else if (i < SX4 + SU4)        { j = i - SX4;             f = u[j];   dst = g_uh;   }
    else if (i < SX4 + SU4 + SW4)  { j = i - SX4 - SU4;       f = win[j]; dst = g_winh; }
    else if (i < TOTAL4)           { j = i - SX4 - SU4 - SW4; f = wr[j];  dst = g_wrh;  }
    else return;
    __half2* o = reinterpret_cast<__half2*>(dst) + j * 2;
    o[0] = __floats2half2_rn(f.x, f.y);
    o[1] = __floats2half2_rn(f.z, f.w);
}

// ---------------------------------------------------------------------------
// Fused GEMM + SfaRNN epilogue (128x128 tile, 2 CTAs/SM, fp16-acc MMA with
// per-chunk fp32 promotion)
// ---------------------------------------------------------------------------
__global__ void __launch_bounds__(NTHREADS, 2)
sfa_rnn_kernel(const float* __restrict__ u,
               const float* __restrict__ v,
               const float* __restrict__ bias,
               float* __restrict__ out) {
    extern __shared__ char smem[];
    const uint32_t sbase = smem_u32(smem);

    const int tid  = threadIdx.x;
    const int wid  = tid >> 5;
    const int lane = tid & 31;
    const int lq   = lane >> 2;
    const int lr   = lane & 3;
    const int wm   = wid & 1;    // M half (64 rows)
    const int wn   = wid >> 1;   // N group of 32 cols (0..3)

    const int nb = blockIdx.x * BN;
    const int mb = blockIdx.y * BM;

    // ---------------- producer geometry ----------------
    const int rbase = tid >> 3;  // 0..31
    const int c16   = tid & 7;   // 16B chunk within 128B row
    const uint32_t swbase =
        (uint32_t)rbase * 128u + ((uint32_t)(c16 ^ (rbase & 7)) << 4);

    const __half* gax = g_xh   + (size_t)(mb + rbase) * DIN   + c16 * 8;
    const __half* gau = g_uh   + (size_t)(mb + rbase) * H_DIM + c16 * 8;
    const __half* gbw = g_winh + (size_t)(nb + rbase) * DIN   + c16 * 8;
    const __half* gbr = g_wrh  + (size_t)(nb + rbase) * H_DIM + c16 * 8;

    auto issue_chunk = [&](int k) {
        const int s = k % STAGES;
        const uint32_t sA = sbase + s * STAGE_BYTES;
        const uint32_t sB = sA + A_BYTES;
        if (k < NKX) {
            const __half* ga = gax + k * BKE;
            const __half* gb = gbw + k * BKE;
#pragma unroll
            for (int i = 0; i < 4; i++)
                cp_async16(sA + swbase + i * 4096u, ga + (size_t)i * 32 * DIN);
#pragma unroll
            for (int i = 0; i < 4; i++)
                cp_async16(sB + swbase + i * 4096u, gb + (size_t)i * 32 * DIN);
        } else {
            const __half* ga = gau + (k - NKX) * BKE;
            const __half* gb = gbr + (k - NKX) * BKE;
#pragma unroll
            for (int i = 0; i < 4; i++)
                cp_async16(sA + swbase + i * 4096u, ga + (size_t)i * 32 * H_DIM);
#pragma unroll
            for (int i = 0; i < 4; i++)
                cp_async16(sB + swbase + i * 4096u, gb + (size_t)i * 32 * H_DIM);
        }
    };

    // ---------------- consumer geometry (ldmatrix) ----------------
    const uint32_t r8   = (uint32_t)(lane & 7);
    const uint32_t a_hi = (uint32_t)(lane >> 4);
    const uint32_t a_m8 = (uint32_t)(((lane >> 3) & 1) << 3);
    const uint32_t b_hi = (uint32_t)((lane >> 3) & 1);
    const uint32_t b_n8 = (uint32_t)((lane >> 4) << 3);

    uint32_t baseA[4];
#pragma unroll
    for (int mi = 0; mi < 4; mi++)
        baseA[mi] = (uint32_t)(wm * 64 + mi * 16) * 128u + (r8 + a_m8) * 128u;
    uint32_t baseB[2];
#pragma unroll
    for (int ni2 = 0; ni2 < 2; ni2++)
        baseB[ni2] = (uint32_t)(wn * 32 + ni2 * 16) * 128u + (r8 + b_n8) * 128u;

    // fp32 master accumulators + per-chunk fp16 accumulators
    float accf[4][4][4];
#pragma unroll
    for (int mi = 0; mi < 4; mi++)
#pragma unroll
        for (int ni = 0; ni < 4; ni++)
#pragma unroll
            for (int r = 0; r < 4; r++) accf[mi][ni][r] = 0.0f;

    // ---------------- prologue ----------------
    issue_chunk(0); cp_commit();
    issue_chunk(1); cp_commit();

    // ---------------- mainloop ----------------
#pragma unroll 1
    for (int k = 0; k < NK; k++) {
        cp_wait<1>();
        __syncthreads();
        if (k + 2 < NK) issue_chunk(k + 2);
        cp_commit();

        const int s = k % STAGES;
        const uint32_t sA = sbase + s * STAGE_BYTES;
        const uint32_t sB = sA + A_BYTES;

        uint32_t acc16[4][4][2];
#pragma unroll
        for (int mi = 0; mi < 4; mi++)
#pragma unroll
            for (int ni = 0; ni < 4; ni++) {
                acc16[mi][ni][0] = 0u;
                acc16[mi][ni][1] = 0u;
            }

#pragma unroll
        for (int ks = 0; ks < 4; ks++) {
            const uint32_t offA = ((2u * (uint32_t)ks + a_hi) ^ r8) << 4;
            const uint32_t offB = ((2u * (uint32_t)ks + b_hi) ^ r8) << 4;

            uint32_t a[4][4];
#pragma unroll
            for (int mi = 0; mi < 4; mi++) LDSM_X4(a[mi], sA + baseA[mi] + offA);
            uint32_t b[2][4];
#pragma unroll
            for (int ni2 = 0; ni2 < 2; ni2++) LDSM_X4(b[ni2], sB + baseB[ni2] + offB);

#pragma unroll
            for (int mi = 0; mi < 4; mi++)
#pragma unroll
                for (int ni = 0; ni < 4; ni++)
                    mma_f16(acc16[mi][ni], a[mi],
                            b[ni >> 1][(ni & 1) * 2 + 0],
                            b[ni >> 1][(ni & 1) * 2 + 1]);
        }

        // promote this chunk's fp16 partial sums into fp32 master accumulators
#pragma unroll
        for (int mi = 0; mi < 4; mi++)
#pragma unroll
            for (int ni = 0; ni < 4; ni++) {
                const float2 lo =
                    __half22float2(*reinterpret_cast<__half2*>(&acc16[mi][ni][0]));
                const float2 hi =
                    __half22float2(*reinterpret_cast<__half2*>(&acc16[mi][ni][1]));
                accf[mi][ni][0] += lo.x;
                accf[mi][ni][1] += lo.y;
                accf[mi][ni][2] += hi.x;
                accf[mi][ni][3] += hi.y;
            }
    }

    // ---------------- fused epilogue ----------------
    const float cu  = 1.0f - (1.0f / 10.0f);
    const float au  = 1.0f / 10.0f;
    const float cv  = 1.0f - (1.0f / 150.0f);
    const float cvm = 10.0f / 150.0f;
    const size_t OUTV = (size_t)B_DIM * H_DIM;

#pragma unroll
    for (int mi = 0; mi < 4; mi++) {
#pragma unroll
        for (int ni = 0; ni < 4; ni++) {
            const int r0 = mb + wm * 64 + mi * 16 + lq;
            const int c  = nb + wn * 32 + ni * 8 + lr * 2;
            const float2 bn = *reinterpret_cast<const float2*>(bias + c);
#pragma unroll
            for (int h = 0; h < 2; h++) {
                const size_t off = (size_t)(r0 + 8 * h) * H_DIM + c;
                const float2 uu = *reinterpret_cast<const float2*>(u + off);
                const float2 vv = *reinterpret_cast<const float2*>(v + off);
                const float g0 = accf[mi][ni][2 * h + 0];
                const float g1 = accf[mi][ni][2 * h + 1];
                const float vn0 = fmaxf(cv * vv.x + cvm * uu.x, 0.0f);
                const float vn1 = fmaxf(cv * vv.y + cvm * uu.y, 0.0f);
                const float un0 = fmaxf(cu * uu.x + au * (g0 + bn.x - vn0), 0.0f);
                const float un1 = fmaxf(cu * uu.y + au * (g1 + bn.y - vn1), 0.0f);
                *reinterpret_cast<float2*>(out + off)        = make_float2(un0, un1);
                *reinterpret_cast<float2*>(out + OUTV + off) = make_float2(vn0, vn1);
            }
        }
    }
}

extern "C" void kernel_launch(void* const* d_in, const int* in_sizes, int n_in,
                              void* d_out, int out_size) {
    (void)in_sizes; (void)n_in; (void)out_size;
    const float* x    = (const float*)d_in[0];
    const float* u    = (const float*)d_in[1];
    const float* v    = (const float*)d_in[2];
    const float* win  = (const float*)d_in[3];
    const float* wr   = (const float*)d_in[4];
    const float* bias = (const float*)d_in[5];
    float* out = (float*)d_out;

    // 1) convert inputs to fp16 scratch
    const int cb = (int)(TOTAL4 / 256);  // 30720 blocks, exact
    convert_kernel<<<cb, 256>>>((const float4*)x, (const float4*)u,
                                (const float4*)win, (const float4*)wr);

    // 2) fused GEMM + epilogue
    cudaFuncSetAttribute(sfa_rnn_kernel,
                         cudaFuncAttributeMaxDynamicSharedMemorySize, SMEM_TOTAL);
    dim3 grid(H_DIM / BN, B_DIM / BM);  // (16, 64) = 1024 CTAs
    sfa_rnn_kernel<<<grid, NTHREADS, SMEM_TOTAL>>>(u, v, bias, out);
}

// round 12
// speedup vs baseline: 1.0749x; 1.0749x over previous
#include <cuda_runtime.h>
#include <cuda_fp16.h>
#include <cstdint>

// Problem dims (fixed by the dataset)
#define B_DIM 8192
#define DIN   1024
#define H_DIM 2048

// Tiling: 128x128 CTA tile, 8 consumer warps (64x32) + 1 producer warp, 2 CTAs/SM
#define BM 128
#define BN 128
#define BKE 64          // fp16 K-elements per chunk = 128B rows (swizzle atom)
#define NK 48           // 3072 / 64
#define NKX 16          // first 16 chunks: x / win (K=1024)
#define STAGES 3
#define NTHREADS 288    // 9 warps

#define A_BYTES (BM * 128)                 // 16 KB
#define B_BYTES (BN * 128)                 // 16 KB
#define STAGE_BYTES (A_BYTES + B_BYTES)    // 32 KB
#define DATA_BYTES (STAGES * STAGE_BYTES)  // 96 KB
#define SMEM_TOTAL (DATA_BYTES + 64)       // + mbarriers

// fp16 copies of the inputs (static scratch; no allocation allowed)
__device__ __half g_xh[(size_t)B_DIM * DIN];
__device__ __half g_uh[(size_t)B_DIM * H_DIM];
__device__ __half g_winh[(size_t)H_DIM * DIN];
__device__ __half g_wrh[(size_t)H_DIM * H_DIM];

__device__ __forceinline__ uint32_t smem_u32(const void* p) {
    uint32_t a;
    asm("{ .reg .u64 t; cvta.to.shared.u64 t, %1; cvt.u32.u64 %0, t; }"
        : "=r"(a) : "l"(p));
    return a;
}

__device__ __forceinline__ void cp_async16(uint32_t saddr, const void* g) {
    asm volatile("cp.async.cg.shared.global [%0], [%1], 16;\n"
                 :: "r"(saddr), "l"(g));
}

__device__ __forceinline__ void mbar_init(uint32_t a, uint32_t cnt) {
    asm volatile("mbarrier.init.shared.b64 [%0], %1;" :: "r"(a), "r"(cnt) : "memory");
}

__device__ __forceinline__ void mbar_arrive(uint32_t a) {
    asm volatile("mbarrier.arrive.shared.b64 _, [%0];" :: "r"(a) : "memory");
}

__device__ __forceinline__ void cp_async_mbar_arrive_noinc(uint32_t a) {
    asm volatile("cp.async.mbarrier.arrive.noinc.shared.b64 [%0];"
                 :: "r"(a) : "memory");
}

__device__ __forceinline__ void mbar_wait(uint32_t a, uint32_t parity) {
    asm volatile(
        "{\n\t"
        ".reg .pred P;\n\t"
        "WAITL_%=:\n\t"
        "mbarrier.try_wait.parity.acquire.cta.shared::cta.b64 P, [%0], %1, 0x989680;\n\t"
        "@P bra.uni WDONE_%=;\n\t"
        "bra.uni WAITL_%=;\n\t"
        "WDONE_%=:\n\t"
        "}"
        :: "r"(a), "r"(parity) : "memory");
}

#define LDSM_X4(r, addr) \
    asm volatile("ldmatrix.sync.aligned.m8n8.x4.shared.b16 {%0,%1,%2,%3}, [%4];" \
        : "=r"((r)[0]), "=r"((r)[1]), "=r"((r)[2]), "=r"((r)[3]) : "r"(addr))

// fp16 inputs, fp32 accumulators
__device__ __forceinline__ void mma_f16f32(float* c, const uint32_t* a,
                                           uint32_t b0, uint32_t b1) {
    asm volatile(
        "mma.sync.aligned.m16n8k16.row.col.f32.f16.f16.f32 "
        "{%0,%1,%2,%3}, {%4,%5,%6,%7}, {%8,%9}, {%0,%1,%2,%3};"
        : "+f"(c[0]), "+f"(c[1]), "+f"(c[2]), "+f"(c[3])
        : "r"(a[0]), "r"(a[1]), "r"(a[2]), "r"(a[3]), "r"(b0), "r"(b1));
}

// ---------------------------------------------------------------------------
// fp32 -> fp16 conversion pre-pass (one float4 per thread)
// ---------------------------------------------------------------------------
#define SX4 ((size_t)B_DIM * DIN / 4)     // 2,097,152
#define SU4 ((size_t)B_DIM * H_DIM / 4)   // 4,194,304
#define SW4 ((size_t)H_DIM * DIN / 4)     //   524,288
#define SR4 ((size_t)H_DIM * H_DIM / 4)   // 1,048,576
#define TOTAL4 (SX4 + SU4 + SW4 + SR4)    // 7,864,320

__global__ void __launch_bounds__(256)
convert_kernel(const float4* __restrict__ x, const float4* __restrict__ u,
               const float4* __restrict__ win, const float4* __restrict__ wr) {
    const size_t i = (size_t)blockIdx.x * blockDim.x + threadIdx.x;
    float4 f;
    __half* dst;
    size_t j;
    if (i < SX4)                   { j = i;                   f = x[j];   dst = g_xh;   }
    else if (i < SX4 + SU4)        { j = i - SX4;             f = u[j];   dst = g_uh;   }
    else if (i < SX4 + SU4 + SW4)  { j = i - SX4 - SU4;       f = win[j]; dst = g_winh; }
    else if (i < TOTAL4)           { j = i - SX4 - SU4 - SW4; f = wr[j];  dst = g_wrh;  }
    else return;
    __half2* o = reinterpret_cast<__half2*>(dst) + j * 2;
    o[0] = __floats2half2_rn(f.x, f.y);
    o[1] = __floats2half2_rn(f.z, f.w);
}

// ---------------------------------------------------------------------------
// Warp-specialized fused GEMM + SfaRNN epilogue
// ---------------------------------------------------------------------------
__global__ void __launch_bounds__(NTHREADS, 2)
sfa_rnn_kernel(const float* __restrict__ u,
               const float* __restrict__ v,
               const float* __restrict__ bias,
               float* __restrict__ out) {
    extern __shared__ char smem[];
    const uint32_t sbase = smem_u32(smem);

    const int tid  = threadIdx.x;
    const int wid  = tid >> 5;
    const int lane = tid & 31;

    const int nb = blockIdx.x * BN;
    const int mb = blockIdx.y * BM;

    // mbarriers: full[s] at DATA+ s*8, free[s] at DATA+24+s*8
    const uint32_t mb_full0 = sbase + DATA_BYTES;
    const uint32_t mb_free0 = sbase + DATA_BYTES + 24;

    if (tid == 0) {
#pragma unroll
        for (int s = 0; s < STAGES; s++) {
            mbar_init(mb_full0 + s * 8, 32);  // 32 producer-thread cp.async arrivals
            mbar_init(mb_free0 + s * 8, 8);   // 8 consumer-warp arrivals
        }
    }
    __syncthreads();

    if (wid == 8) {
        // ================= PRODUCER WARP =================
        // Each thread: 32 A cp.asyncs + 32 B cp.asyncs per chunk.
        // lane -> (prow = lane>>3 in 0..3, pc16 = lane&7); rows prow+4*i.
        const int prow = lane >> 3;
        const int pc16 = lane & 7;

        uint32_t swoff[32];
#pragma unroll
        for (int i = 0; i < 32; i++) {
            const uint32_t row = (uint32_t)(prow + 4 * i);
            swoff[i] = row * 128u + (((uint32_t)pc16 ^ (row & 7u)) << 4);
        }
        const __half* gax = g_xh   + (size_t)(mb + prow) * DIN   + pc16 * 8;
        const __half* gau = g_uh   + (size_t)(mb + prow) * H_DIM + pc16 * 8;
        const __half* gbw = g_winh + (size_t)(nb + prow) * DIN   + pc16 * 8;
        const __half* gbr = g_wrh  + (size_t)(nb + prow) * H_DIM + pc16 * 8;

        int es = 0, ephase = 0;   // free-barrier cursor (for chunk j>=3)
        int ss = 0;               // stage cursor
#pragma unroll 1
        for (int j = 0; j < NK; j++) {
            if (j >= STAGES) {
                mbar_wait(mb_free0 + es * 8, ephase);
                if (++es == STAGES) { es = 0; ephase ^= 1; }
            }
            const uint32_t sA = sbase + ss * STAGE_BYTES;
            const uint32_t sB = sA + A_BYTES;
            if (j < NKX) {
                const __half* ga = gax + j * BKE;
                const __half* gb = gbw + j * BKE;
#pragma unroll 8
                for (int i = 0; i < 32; i++)
                    cp_async16(sA + swoff[i], ga + (size_t)(4 * i) * DIN);
#pragma unroll 8
                for (int i = 0; i < 32; i++)
                    cp_async16(sB + swoff[i], gb + (size_t)(4 * i) * DIN);
            } else {
                const __half* ga = gau + (j - NKX) * BKE;
                const __half* gb = gbr + (j - NKX) * BKE;
#pragma unroll 8
                for (int i = 0; i < 32; i++)
                    cp_async16(sA + swoff[i], ga + (size_t)(4 * i) * H_DIM);
#pragma unroll 8
                for (int i = 0; i < 32; i++)
                    cp_async16(sB + swoff[i], gb + (size_t)(4 * i) * H_DIM);
            }
            cp_async_mbar_arrive_noinc(mb_full0 + ss * 8);
            if (++ss == STAGES) ss = 0;
        }
        return;  // producer done; consumers handle epilogue
    }

    // ================= CONSUMER WARPS (0..7) =================
    const int lq = lane >> 2;
    const int lr = lane & 3;
    const int wm = wid & 1;    // M half (64 rows)
    const int wn = wid >> 1;   // N group of 32 cols (0..3)

    const uint32_t r8   = (uint32_t)(lane & 7);
    const uint32_t a_hi = (uint32_t)(lane >> 4);
    const uint32_t a_m8 = (uint32_t)(((lane >> 3) & 1) << 3);
    const uint32_t b_hi = (uint32_t)((lane >> 3) & 1);
    const uint32_t b_n8 = (uint32_t)((lane >> 4) << 3);

    uint32_t baseA[4];
#pragma unroll
    for (int mi = 0; mi < 4; mi++)
        baseA[mi] = (uint32_t)(wm * 64 + mi * 16) * 128u + (r8 + a_m8) * 128u;
    uint32_t baseB[2];
#pragma unroll
    for (int ni2 = 0; ni2 < 2; ni2++)
        baseB[ni2] = (uint32_t)(wn * 32 + ni2 * 16) * 128u + (r8 + b_n8) * 128u;

    float acc[4][4][4];
#pragma unroll
    for (int mi = 0; mi < 4; mi++)
#pragma unroll
        for (int ni = 0; ni < 4; ni++)
#pragma unroll
            for (int r = 0; r < 4; r++) acc[mi][ni][r] = 0.0f;

    int fs = 0, fphase = 0;  // full-barrier cursor
#pragma unroll 1
    for (int k = 0; k < NK; k++) {
        mbar_wait(mb_full0 + fs * 8, fphase);
        const uint32_t sA = sbase + fs * STAGE_BYTES;
        const uint32_t sB = sA + A_BYTES;

#pragma unroll
        for (int ks = 0; ks < 4; ks++) {
            const uint32_t offA = ((2u * (uint32_t)ks + a_hi) ^ r8) << 4;
            const uint32_t offB = ((2u * (uint32_t)ks + b_hi) ^ r8) << 4;

            uint32_t a[4][4];
#pragma unroll
            for (int mi = 0; mi < 4; mi++) LDSM_X4(a[mi], sA + baseA[mi] + offA);
            uint32_t b[2][4];
#pragma unroll
            for (int ni2 = 0; ni2 < 2; ni2++) LDSM_X4(b[ni2], sB + baseB[ni2] + offB);

#pragma unroll
            for (int mi = 0; mi < 4; mi++)
#pragma unroll
                for (int ni = 0; ni < 4; ni++)
                    mma_f16f32(acc[mi][ni], a[mi],
                               b[ni >> 1][(ni & 1) * 2 + 0],
                               b[ni >> 1][(ni & 1) * 2 + 1]);
        }
        // all LDSM reads of this stage are complete (synchronous) -> release
        if (lane == 0) mbar_arrive(mb_free0 + fs * 8);
        if (++fs == STAGES) { fs = 0; fphase ^= 1; }
    }

    // ---------------- fused epilogue ----------------
    const float cu  = 1.0f - (1.0f / 10.0f);
    const float au  = 1.0f / 10.0f;
    const float cv  = 1.0f - (1.0f / 150.0f);
    const float cvm = 10.0f / 150.0f;
    const size_t OUTV = (size_t)B_DIM * H_DIM;

#pragma unroll
    for (int mi = 0; mi < 4; mi++) {
#pragma unroll
        for (int ni = 0; ni < 4; ni++) {
            const int r0 = mb + wm * 64 + mi * 16 + lq;
            const int c  = nb + wn * 32 + ni * 8 + lr * 2;
            const float2 bn = *reinterpret_cast<const float2*>(bias + c);
#pragma unroll
            for (int h = 0; h < 2; h++) {
                const size_t off = (size_t)(r0 + 8 * h) * H_DIM + c;
                const float2 uu = *reinterpret_cast<const float2*>(u + off);
                const float2 vv = *reinterpret_cast<const float2*>(v + off);
                const float g0 = acc[mi][ni][2 * h + 0];
                const float g1 = acc[mi][ni][2 * h + 1];
                const float vn0 = fmaxf(cv * vv.x + cvm * uu.x, 0.0f);
                const float vn1 = fmaxf(cv * vv.y + cvm * uu.y, 0.0f);
                const float un0 = fmaxf(cu * uu.x + au * (g0 + bn.x - vn0), 0.0f);
                const float un1 = fmaxf(cu * uu.y + au * (g1 + bn.y - vn1), 0.0f);
                *reinterpret_cast<float2*>(out + off)        = make_float2(un0, un1);
                *reinterpret_cast<float2*>(out + OUTV + off) = make_float2(vn0, vn1);
            }
        }
    }
}

extern "C" void kernel_launch(void* const* d_in, const int* in_sizes, int n_in,
                              void* d_out, int out_size) {
    (void)in_sizes; (void)n_in; (void)out_size;
    const float* x    = (const float*)d_in[0];
    const float* u    = (const float*)d_in[1];
    const float* v    = (const float*)d_in[2];
    const float* win  = (const float*)d_in[3];
    const float* wr   = (const float*)d_in[4];
    const float* bias = (const float*)d_in[5];
    float* out = (float*)d_out;

    // 1) convert inputs to fp16 scratch
    const int cb = (int)(TOTAL4 / 256);  // 30720 blocks, exact
    convert_kernel<<<cb, 256>>>((const float4*)x, (const float4*)u,
                                (const float4*)win, (const float4*)wr);

    // 2) warp-specialized fused GEMM + epilogue
    cudaFuncSetAttribute(sfa_rnn_kernel,
                         cudaFuncAttributeMaxDynamicSharedMemorySize, SMEM_TOTAL);
    dim3 grid(H_DIM / BN, B_DIM / BM);  // (16, 64) = 1024 CTAs
    sfa_rnn_kernel<<<grid, NTHREADS, SMEM_TOTAL>>>(u, v, bias, out);
}

// round 13
// speedup vs baseline: 1.2642x; 1.1761x over previous
#include <cuda_runtime.h>
#include <cuda_fp16.h>
#include <cstdint>

// Problem dims (fixed by the dataset)
#define B_DIM 8192
#define DIN   1024
#define H_DIM 2048

// Tiling: 128x128 CTA tile, 8 consumer warps (64x32) + 2 producer warps, 2 CTAs/SM
#define BM 128
#define BN 128
#define BKE 64          // fp16 K-elements per chunk = 128B rows (swizzle atom)
#define NK 48           // 3072 / 64
#define NKX 16          // first 16 chunks: x / win (K=1024)
#define STAGES 3
#define NTHREADS 320    // 10 warps: 8 consumers + 2 producers

#define A_BYTES (BM * 128)                 // 16 KB
#define B_BYTES (BN * 128)                 // 16 KB
#define STAGE_BYTES (A_BYTES + B_BYTES)    // 32 KB
#define DATA_BYTES (STAGES * STAGE_BYTES)  // 96 KB
#define SMEM_TOTAL (DATA_BYTES + 64)       // + mbarriers

// fp16 copies of the inputs (static scratch; no allocation allowed)
__device__ __half g_xh[(size_t)B_DIM * DIN];
__device__ __half g_uh[(size_t)B_DIM * H_DIM];
__device__ __half g_winh[(size_t)H_DIM * DIN];
__device__ __half g_wrh[(size_t)H_DIM * H_DIM];

__device__ __forceinline__ uint32_t smem_u32(const void* p) {
    uint32_t a;
    asm("{ .reg .u64 t; cvta.to.shared.u64 t, %1; cvt.u32.u64 %0, t; }"
        : "=r"(a) : "l"(p));
    return a;
}

__device__ __forceinline__ void cp_async16(uint32_t saddr, const void* g) {
    asm volatile("cp.async.cg.shared.global [%0], [%1], 16;\n"
                 :: "r"(saddr), "l"(g));
}

__device__ __forceinline__ void mbar_init(uint32_t a, uint32_t cnt) {
    asm volatile("mbarrier.init.shared.b64 [%0], %1;" :: "r"(a), "r"(cnt) : "memory");
}

__device__ __forceinline__ void mbar_arrive(uint32_t a) {
    asm volatile("mbarrier.arrive.shared.b64 _, [%0];" :: "r"(a) : "memory");
}

__device__ __forceinline__ void cp_async_mbar_arrive_noinc(uint32_t a) {
    asm volatile("cp.async.mbarrier.arrive.noinc.shared.b64 [%0];"
                 :: "r"(a) : "memory");
}

__device__ __forceinline__ void mbar_wait(uint32_t a, uint32_t parity) {
    asm volatile(
        "{\n\t"
        ".reg .pred P;\n\t"
        "WAITL_%=:\n\t"
        "mbarrier.try_wait.parity.acquire.cta.shared::cta.b64 P, [%0], %1, 0x989680;\n\t"
        "@P bra.uni WDONE_%=;\n\t"
        "bra.uni WAITL_%=;\n\t"
        "WDONE_%=:\n\t"
        "}"
        :: "r"(a), "r"(parity) : "memory");
}

#define LDSM_X4(r, addr) \
    asm volatile("ldmatrix.sync.aligned.m8n8.x4.shared.b16 {%0,%1,%2,%3}, [%4];" \
        : "=r"((r)[0]), "=r"((r)[1]), "=r"((r)[2]), "=r"((r)[3]) : "r"(addr))

// fp16 inputs, fp32 accumulators
__device__ __forceinline__ void mma_f16f32(float* c, const uint32_t* a,
                                           uint32_t b0, uint32_t b1) {
    asm volatile(
        "mma.sync.aligned.m16n8k16.row.col.f32.f16.f16.f32 "
        "{%0,%1,%2,%3}, {%4,%5,%6,%7}, {%8,%9}, {%0,%1,%2,%3};"
        : "+f"(c[0]), "+f"(c[1]), "+f"(c[2]), "+f"(c[3])
        : "r"(a[0]), "r"(a[1]), "r"(a[2]), "r"(a[3]), "r"(b0), "r"(b1));
}

// ---------------------------------------------------------------------------
// fp32 -> fp16 conversion pre-pass (one float4 per thread)
// ---------------------------------------------------------------------------
#define SX4 ((size_t)B_DIM * DIN / 4)     // 2,097,152
#define SU4 ((size_t)B_DIM * H_DIM / 4)   // 4,194,304
#define SW4 ((size_t)H_DIM * DIN / 4)     //   524,288
#define SR4 ((size_t)H_DIM * H_DIM / 4)   // 1,048,576
#define TOTAL4 (SX4 + SU4 + SW4 + SR4)    // 7,864,320

__global__ void __launch_bounds__(256)
convert_kernel(const float4* __restrict__ x, const float4* __restrict__ u,
               const float4* __restrict__ win, const float4* __restrict__ wr) {
    const size_t i = (size_t)blockIdx.x * blockDim.x + threadIdx.x;
    float4 f;
    __half* dst;
    size_t j;
    if (i < SX4)                   { j = i;                   f = x[j];   dst = g_xh;   }
    else if (i < SX4 + SU4)        { j = i - SX4;             f = u[j];   dst = g_uh;   }
    else if (i < SX4 + SU4 + SW4)  { j = i - SX4 - SU4;       f = win[j]; dst = g_winh; }
    else if (i < TOTAL4)           { j = i - SX4 - SU4 - SW4; f = wr[j];  dst = g_wrh;  }
    else return;
    __half2* o = reinterpret_cast<__half2*>(dst) + j * 2;
    o[0] = __floats2half2_rn(f.x, f.y);
    o[1] = __floats2half2_rn(f.z, f.w);
}

// ---------------------------------------------------------------------------
// Warp-specialized fused GEMM + SfaRNN epilogue (2 producer warps, 2 CTAs/SM)
// ---------------------------------------------------------------------------
__global__ void __launch_bounds__(NTHREADS, 2)
sfa_rnn_kernel(const float* __restrict__ u,
               const float* __restrict__ v,
               const float* __restrict__ bias,
               float* __restrict__ out) {
    extern __shared__ char smem[];
    const uint32_t sbase = smem_u32(smem);

    const int tid  = threadIdx.x;
    const int wid  = tid >> 5;
    const int lane = tid & 31;

    const int nb = blockIdx.x * BN;
    const int mb = blockIdx.y * BM;

    // mbarriers: full[s] at DATA + s*8, free[s] at DATA + 24 + s*8
    const uint32_t mb_full0 = sbase + DATA_BYTES;
    const uint32_t mb_free0 = sbase + DATA_BYTES + 24;

    if (tid == 0) {
#pragma unroll
        for (int s = 0; s < STAGES; s++) {
            mbar_init(mb_full0 + s * 8, 64);  // 64 producer-thread cp.async arrivals
            mbar_init(mb_free0 + s * 8, 8);   // 8 consumer-warp arrivals
        }
    }
    __syncthreads();

    if (wid >= 8) {
        // ================= PRODUCER WARPS (wid 8,9; 64 threads) =================
        // Each thread: 16 A + 16 B cp.asyncs per chunk.
        const int pt   = tid - 256;   // 0..63
        const int prow = pt >> 3;     // 0..7
        const int pc16 = pt & 7;      // 16B chunk within 128B row

        uint32_t swoff[16];
#pragma unroll
        for (int i = 0; i < 16; i++) {
            const uint32_t row = (uint32_t)(prow + 8 * i);
            swoff[i] = row * 128u + (((uint32_t)pc16 ^ (row & 7u)) << 4);
        }
        const __half* gax = g_xh   + (size_t)(mb + prow) * DIN   + pc16 * 8;
        const __half* gau = g_uh   + (size_t)(mb + prow) * H_DIM + pc16 * 8;
        const __half* gbw = g_winh + (size_t)(nb + prow) * DIN   + pc16 * 8;
        const __half* gbr = g_wrh  + (size_t)(nb + prow) * H_DIM + pc16 * 8;

        int es = 0, ephase = 0;   // free-barrier cursor (for chunk j >= STAGES)
        int ss = 0;               // stage cursor
#pragma unroll 1
        for (int j = 0; j < NK; j++) {
            if (j >= STAGES) {
                mbar_wait(mb_free0 + es * 8, ephase);
                if (++es == STAGES) { es = 0; ephase ^= 1; }
            }
            const uint32_t sA = sbase + ss * STAGE_BYTES;
            const uint32_t sB = sA + A_BYTES;
            if (j < NKX) {
                const __half* ga = gax + j * BKE;
                const __half* gb = gbw + j * BKE;
#pragma unroll
                for (int i = 0; i < 16; i++)
                    cp_async16(sA + swoff[i], ga + (size_t)(8 * i) * DIN);
#pragma unroll
                for (int i = 0; i < 16; i++)
                    cp_async16(sB + swoff[i], gb + (size_t)(8 * i) * DIN);
            } else {
                const __half* ga = gau + (j - NKX) * BKE;
                const __half* gb = gbr + (j - NKX) * BKE;
#pragma unroll
                for (int i = 0; i < 16; i++)
                    cp_async16(sA + swoff[i], ga + (size_t)(8 * i) * H_DIM);
#pragma unroll
                for (int i = 0; i < 16; i++)
                    cp_async16(sB + swoff[i], gb + (size_t)(8 * i) * H_DIM);
            }
            cp_async_mbar_arrive_noinc(mb_full0 + ss * 8);
            if (++ss == STAGES) ss = 0;
        }
        return;  // producers done; consumers handle epilogue
    }

    // ================= CONSUMER WARPS (0..7) =================
    const int lq = lane >> 2;
    const int lr = lane & 3;
    const int wm = wid & 1;    // M half (64 rows)
    const int wn = wid >> 1;   // N group of 32 cols (0..3)

    const uint32_t r8   = (uint32_t)(lane & 7);
    const uint32_t a_hi = (uint32_t)(lane >> 4);
    const uint32_t a_m8 = (uint32_t)(((lane >> 3) & 1) << 3);
    const uint32_t b_hi = (uint32_t)((lane >> 3) & 1);
    const uint32_t b_n8 = (uint32_t)((lane >> 4) << 3);

    uint32_t baseA[4];
#pragma unroll
    for (int mi = 0; mi < 4; mi++)
        baseA[mi] = (uint32_t)(wm * 64 + mi * 16) * 128u + (r8 + a_m8) * 128u;
    uint32_t baseB[2];
#pragma unroll
    for (int ni2 = 0; ni2 < 2; ni2++)
        baseB[ni2] = (uint32_t)(wn * 32 + ni2 * 16) * 128u + (r8 + b_n8) * 128u;

    float acc[4][4][4];
#pragma unroll
    for (int mi = 0; mi < 4; mi++)
#pragma unroll
        for (int ni = 0; ni < 4; ni++)
#pragma unroll
            for (int r = 0; r < 4; r++) acc[mi][ni][r] = 0.0f;

    int fs = 0, fphase = 0;  // full-barrier cursor
#pragma unroll 1
    for (int k = 0; k < NK; k++) {
        mbar_wait(mb_full0 + fs * 8, fphase);
        const uint32_t sA = sbase + fs * STAGE_BYTES;
        const uint32_t sB = sA + A_BYTES;

#pragma unroll
        for (int ks = 0; ks < 4; ks++) {
            const uint32_t offA = ((2u * (uint32_t)ks + a_hi) ^ r8) << 4;
            const uint32_t offB = ((2u * (uint32_t)ks + b_hi) ^ r8) << 4;

            uint32_t a[4][4];
#pragma unroll
            for (int mi = 0; mi < 4; mi++) LDSM_X4(a[mi], sA + baseA[mi] + offA);
            uint32_t b[2][4];
#pragma unroll
            for (int ni2 = 0; ni2 < 2; ni2++) LDSM_X4(b[ni2], sB + baseB[ni2] + offB);

#pragma unroll
            for (int mi = 0; mi < 4; mi++)
#pragma unroll
                for (int ni = 0; ni < 4; ni++)
                    mma_f16f32(acc[mi][ni], a[mi],
                               b[ni >> 1][(ni & 1) * 2 + 0],
                               b[ni >> 1][(ni & 1) * 2 + 1]);
        }
        // all LDSM reads of this stage are complete (synchronous) -> release
        if (lane == 0) mbar_arrive(mb_free0 + fs * 8);
        if (++fs == STAGES) { fs = 0; fphase ^= 1; }
    }

    // ---------------- fused epilogue ----------------
    const float cu  = 1.0f - (1.0f / 10.0f);
    const float au  = 1.0f / 10.0f;
    const float cv  = 1.0f - (1.0f / 150.0f);
    const float cvm = 10.0f / 150.0f;
    const size_t OUTV = (size_t)B_DIM * H_DIM;

#pragma unroll
    for (int mi = 0; mi < 4; mi++) {
#pragma unroll
        for (int ni = 0; ni < 4; ni++) {
            const int r0 = mb + wm * 64 + mi * 16 + lq;
            const int c  = nb + wn * 32 + ni * 8 + lr * 2;
            const float2 bn = *reinterpret_cast<const float2*>(bias + c);
#pragma unroll
            for (int h = 0; h < 2; h++) {
                const size_t off = (size_t)(r0 + 8 * h) * H_DIM + c;
                const float2 uu = *reinterpret_cast<const float2*>(u + off);
                const float2 vv = *reinterpret_cast<const float2*>(v + off);
                const float g0 = acc[mi][ni][2 * h + 0];
                const float g1 = acc[mi][ni][2 * h + 1];
                const float vn0 = fmaxf(cv * vv.x + cvm * uu.x, 0.0f);
                const float vn1 = fmaxf(cv * vv.y + cvm * uu.y, 0.0f);
                const float un0 = fmaxf(cu * uu.x + au * (g0 + bn.x - vn0), 0.0f);
                const float un1 = fmaxf(cu * uu.y + au * (g1 + bn.y - vn1), 0.0f);
                *reinterpret_cast<float2*>(out + off)        = make_float2(un0, un1);
                *reinterpret_cast<float2*>(out + OUTV + off) = make_float2(vn0, vn1);
            }
        }
    }
}

extern "C" void kernel_launch(void* const* d_in, const int* in_sizes, int n_in,
                              void* d_out, int out_size) {
    (void)in_sizes; (void)n_in; (void)out_size;
    const float* x    = (const float*)d_in[0];
    const float* u    = (const float*)d_in[1];
    const float* v    = (const float*)d_in[2];
    const float* win  = (const float*)d_in[3];
    const float* wr   = (const float*)d_in[4];
    const float* bias = (const float*)d_in[5];
    float* out = (float*)d_out;

    // 1) convert inputs to fp16 scratch
    const int cb = (int)(TOTAL4 / 256);  // 30720 blocks, exact
    convert_kernel<<<cb, 256>>>((const float4*)x, (const float4*)u,
                                (const float4*)win, (const float4*)wr);

    // 2) warp-specialized fused GEMM + epilogue
    cudaFuncSetAttribute(sfa_rnn_kernel,
                         cudaFuncAttributeMaxDynamicSharedMemorySize, SMEM_TOTAL);
    dim3 grid(H_DIM / BN, B_DIM / BM);  // (16, 64) = 1024 CTAs
    sfa_rnn_kernel<<<grid, NTHREADS, SMEM_TOTAL>>>(u, v, bias, out);
}

// round 14
// speedup vs baseline: 1.3286x; 1.0510x over previous
#include <cuda_runtime.h>
#include <cuda_fp16.h>
#include <cstdint>

// Problem dims (fixed by the dataset)
#define B_DIM 8192
#define DIN   1024
#define H_DIM 2048

// Tiling: 128x128 CTA tile, 8 consumer warps (64x32) + 2 producer warps, 2 CTAs/SM
#define BM 128
#define BN 128
#define BKE 64          // fp16 K-elements per chunk = 128B rows (swizzle atom)
#define NK 48           // 3072 / 64
#define NKX 16          // first 16 chunks: x / win (K=1024)
#define STAGES 3
#define NTHREADS 320    // 10 warps: 8 consumers + 2 producers

#define A_BYTES (BM * 128)                 // 16 KB
#define B_BYTES (BN * 128)                 // 16 KB
#define STAGE_BYTES (A_BYTES + B_BYTES)    // 32 KB
#define DATA_BYTES (STAGES * STAGE_BYTES)  // 96 KB
#define SMEM_TOTAL (DATA_BYTES + 64)       // + mbarriers

// fp16 copies of the inputs (static scratch; no allocation allowed)
__device__ __half g_xh[(size_t)B_DIM * DIN];
__device__ __half g_uh[(size_t)B_DIM * H_DIM];
__device__ __half g_winh[(size_t)H_DIM * DIN];
__device__ __half g_wrh[(size_t)H_DIM * H_DIM];

__device__ __forceinline__ uint32_t smem_u32(const void* p) {
    uint32_t a;
    asm("{ .reg .u64 t; cvta.to.shared.u64 t, %1; cvt.u32.u64 %0, t; }"
        : "=r"(a) : "l"(p));
    return a;
}

__device__ __forceinline__ void cp_async16(uint32_t saddr, const void* g) {
    asm volatile("cp.async.cg.shared.global [%0], [%1], 16;\n"
                 :: "r"(saddr), "l"(g));
}

__device__ __forceinline__ void mbar_init(uint32_t a, uint32_t cnt) {
    asm volatile("mbarrier.init.shared.b64 [%0], %1;" :: "r"(a), "r"(cnt) : "memory");
}

__device__ __forceinline__ void mbar_arrive(uint32_t a) {
    asm volatile("mbarrier.arrive.shared.b64 _, [%0];" :: "r"(a) : "memory");
}

__device__ __forceinline__ void cp_async_mbar_arrive_noinc(uint32_t a) {
    asm volatile("cp.async.mbarrier.arrive.noinc.shared.b64 [%0];"
                 :: "r"(a) : "memory");
}

__device__ __forceinline__ void mbar_wait(uint32_t a, uint32_t parity) {
    asm volatile(
        "{\n\t"
        ".reg .pred P;\n\t"
        "WAITL_%=:\n\t"
        "mbarrier.try_wait.parity.acquire.cta.shared::cta.b64 P, [%0], %1, 0x989680;\n\t"
        "@P bra.uni WDONE_%=;\n\t"
        "bra.uni WAITL_%=;\n\t"
        "WDONE_%=:\n\t"
        "}"
        :: "r"(a), "r"(parity) : "memory");
}

// relaxed wait: post-wait accesses are async-proxy only (cp.async fills)
__device__ __forceinline__ void mbar_wait_relaxed(uint32_t a, uint32_t parity) {
    asm volatile(
        "{\n\t"
        ".reg .pred P;\n\t"
        "WAITL_%=:\n\t"
        "mbarrier.try_wait.parity.relaxed.cta.shared::cta.b64 P, [%0], %1, 0x989680;\n\t"
        "@P bra.uni WDONE_%=;\n\t"
        "bra.uni WAITL_%=;\n\t"
        "WDONE_%=:\n\t"
        "}"
        :: "r"(a), "r"(parity) : "memory");
}

#define LDSM_X4(r, addr) \
    asm volatile("ldmatrix.sync.aligned.m8n8.x4.shared.b16 {%0,%1,%2,%3}, [%4];" \
        : "=r"((r)[0]), "=r"((r)[1]), "=r"((r)[2]), "=r"((r)[3]) : "r"(addr))

// fp16 inputs, fp32 accumulators
__device__ __forceinline__ void mma_f16f32(float* c, const uint32_t* a,
                                           uint32_t b0, uint32_t b1) {
    asm volatile(
        "mma.sync.aligned.m16n8k16.row.col.f32.f16.f16.f32 "
        "{%0,%1,%2,%3}, {%4,%5,%6,%7}, {%8,%9}, {%0,%1,%2,%3};"
        : "+f"(c[0]), "+f"(c[1]), "+f"(c[2]), "+f"(c[3])
        : "r"(a[0]), "r"(a[1]), "r"(a[2]), "r"(a[3]), "r"(b0), "r"(b1));
}

// ---------------------------------------------------------------------------
// fp32 -> fp16 conversion pre-pass (one float4 per thread)
// ---------------------------------------------------------------------------
#define SX4 ((size_t)B_DIM * DIN / 4)     // 2,097,152
#define SU4 ((size_t)B_DIM * H_DIM / 4)   // 4,194,304
#define SW4 ((size_t)H_DIM * DIN / 4)     //   524,288
#define SR4 ((size_t)H_DIM * H_DIM / 4)   // 1,048,576
#define TOTAL4 (SX4 + SU4 + SW4 + SR4)    // 7,864,320

__global__ void __launch_bounds__(256)
convert_kernel(const float4* __restrict__ x, const float4* __restrict__ u,
               const float4* __restrict__ win, const float4* __restrict__ wr) {
    const size_t i = (size_t)blockIdx.x * blockDim.x + threadIdx.x;
    float4 f;
    __half* dst;
    size_t j;
    if (i < SX4)                   { j = i;                   f = x[j];   dst = g_xh;   }
    else if (i < SX4 + SU4)        { j = i - SX4;             f = u[j];   dst = g_uh;   }
    else if (i < SX4 + SU4 + SW4)  { j = i - SX4 - SU4;       f = win[j]; dst = g_winh; }
    else if (i < TOTAL4)           { j = i - SX4 - SU4 - SW4; f = wr[j];  dst = g_wrh;  }
    else return;
    __half2* o = reinterpret_cast<__half2*>(dst) + j * 2;
    o[0] = __floats2half2_rn(f.x, f.y);
    o[1] = __floats2half2_rn(f.z, f.w);
}

// ---------------------------------------------------------------------------
// Warp-specialized fused GEMM + SfaRNN epilogue
// (2 producer warps, 2 CTAs/SM, mi-pipelined fragments, x3-unrolled mainloop)
// ---------------------------------------------------------------------------
__global__ void __launch_bounds__(NTHREADS, 2)
sfa_rnn_kernel(const float* __restrict__ u,
               const float* __restrict__ v,
               const float* __restrict__ bias,
               float* __restrict__ out) {
    extern __shared__ char smem[];
    const uint32_t sbase = smem_u32(smem);

    const int tid  = threadIdx.x;
    const int wid  = tid >> 5;
    const int lane = tid & 31;

    const int nb = blockIdx.x * BN;
    const int mb = blockIdx.y * BM;

    // mbarriers: full[s] at DATA + s*8, free[s] at DATA + 24 + s*8
    const uint32_t mb_full0 = sbase + DATA_BYTES;
    const uint32_t mb_free0 = sbase + DATA_BYTES + 24;

    if (tid == 0) {
#pragma unroll
        for (int s = 0; s < STAGES; s++) {
            mbar_init(mb_full0 + s * 8, 64);  // 64 producer-thread cp.async arrivals
            mbar_init(mb_free0 + s * 8, 8);   // 8 consumer-warp arrivals
        }
    }
    __syncthreads();

    if (wid >= 8) {
        // ================= PRODUCER WARPS (wid 8,9; 64 threads) =================
        const int pt   = tid - 256;   // 0..63
        const int prow = pt >> 3;     // 0..7
        const int pc16 = pt & 7;      // 16B chunk within 128B row

        uint32_t swoff[16];
#pragma unroll
        for (int i = 0; i < 16; i++) {
            const uint32_t row = (uint32_t)(prow + 8 * i);
            swoff[i] = row * 128u + (((uint32_t)pc16 ^ (row & 7u)) << 4);
        }
        const __half* gax = g_xh   + (size_t)(mb + prow) * DIN   + pc16 * 8;
        const __half* gau = g_uh   + (size_t)(mb + prow) * H_DIM + pc16 * 8;
        const __half* gbw = g_winh + (size_t)(nb + prow) * DIN   + pc16 * 8;
        const __half* gbr = g_wrh  + (size_t)(nb + prow) * H_DIM + pc16 * 8;

        int ephase = 0;
#pragma unroll 1
        for (int jj = 0; jj < NK; jj += STAGES) {
#pragma unroll
            for (int s = 0; s < STAGES; s++) {
                const int j = jj + s;
                if (j >= STAGES) mbar_wait_relaxed(mb_free0 + s * 8, ephase);
                const uint32_t sA = sbase + s * STAGE_BYTES;
                const uint32_t sB = sA + A_BYTES;
                if (j < NKX) {
                    const __half* ga = gax + j * BKE;
                    const __half* gb = gbw + j * BKE;
#pragma unroll
                    for (int i = 0; i < 16; i++)
                        cp_async16(sA + swoff[i], ga + (size_t)(8 * i) * DIN);
#pragma unroll
                    for (int i = 0; i < 16; i++)
                        cp_async16(sB + swoff[i], gb + (size_t)(8 * i) * DIN);
                } else {
                    const __half* ga = gau + (j - NKX) * BKE;
                    const __half* gb = gbr + (j - NKX) * BKE;
#pragma unroll
                    for (int i = 0; i < 16; i++)
                        cp_async16(sA + swoff[i], ga + (size_t)(8 * i) * H_DIM);
#pragma unroll
                    for (int i = 0; i < 16; i++)
                        cp_async16(sB + swoff[i], gb + (size_t)(8 * i) * H_DIM);
                }
                cp_async_mbar_arrive_noinc(mb_full0 + s * 8);
            }
            if (jj >= STAGES) ephase ^= 1;  // first wait group (jj==3) uses phase 0
        }
        return;  // producers done; consumers handle epilogue
    }

    // ================= CONSUMER WARPS (0..7) =================
    const int lq = lane >> 2;
    const int lr = lane & 3;
    const int wm = wid & 1;    // M half (64 rows)
    const int wn = wid >> 1;   // N group of 32 cols (0..3)

    const uint32_t r8   = (uint32_t)(lane & 7);
    const uint32_t a_hi = (uint32_t)(lane >> 4);
    const uint32_t a_m8 = (uint32_t)(((lane >> 3) & 1) << 3);
    const uint32_t b_hi = (uint32_t)((lane >> 3) & 1);
    const uint32_t b_n8 = (uint32_t)((lane >> 4) << 3);

    uint32_t baseA[4];
#pragma unroll
    for (int mi = 0; mi < 4; mi++)
        baseA[mi] = (uint32_t)(wm * 64 + mi * 16) * 128u + (r8 + a_m8) * 128u;
    uint32_t baseB[2];
#pragma unroll
    for (int ni2 = 0; ni2 < 2; ni2++)
        baseB[ni2] = (uint32_t)(wn * 32 + ni2 * 16) * 128u + (r8 + b_n8) * 128u;

    float acc[4][4][4];
#pragma unroll
    for (int mi = 0; mi < 4; mi++)
#pragma unroll
        for (int ni = 0; ni < 4; ni++)
#pragma unroll
            for (int r = 0; r < 4; r++) acc[mi][ni][r] = 0.0f;

    int fphase = 0;
#pragma unroll 1
    for (int kk = 0; kk < NK; kk += STAGES) {
#pragma unroll
        for (int s = 0; s < STAGES; s++) {
            mbar_wait(mb_full0 + s * 8, fphase);
            const uint32_t sA = sbase + s * STAGE_BYTES;
            const uint32_t sB = sA + A_BYTES;

#pragma unroll
            for (int ks = 0; ks < 4; ks++) {
                const uint32_t offA = ((2u * (uint32_t)ks + a_hi) ^ r8) << 4;
                const uint32_t offB = ((2u * (uint32_t)ks + b_hi) ^ r8) << 4;

                // B fragments for this ks (8 regs)
                uint32_t b0[4], b1[4];
                LDSM_X4(b0, sB + baseB[0] + offB);
                LDSM_X4(b1, sB + baseB[1] + offB);

                // mi-pipelined A fragments: 2 buffers (8 regs), prefetch
                // a(mi+1) between the MMA quads of mi
                uint32_t a2[2][4];
                LDSM_X4(a2[0], sA + baseA[0] + offA);
#pragma unroll
                for (int mi = 0; mi < 4; mi++) {
                    if (mi < 3) LDSM_X4(a2[(mi + 1) & 1], sA + baseA[mi + 1] + offA);
                    const uint32_t* am = a2[mi & 1];
                    mma_f16f32(acc[mi][0], am, b0[0], b0[1]);
                    // Early release: all LDSM of this stage are issued and the
                    // MMA above consumes the last-loaded fragment buffer's
                    // sibling path; the producer's refill (cp.async via L2,
                    // >500 cyc away) cannot race the in-flight LDSM reads.
                    if (ks == 3 && mi == 3 && lane == 0)
                        mbar_arrive(mb_free0 + s * 8);
                    mma_f16f32(acc[mi][1], am, b0[2], b0[3]);
                    mma_f16f32(acc[mi][2], am, b1[0], b1[1]);
                    mma_f16f32(acc[mi][3], am, b1[2], b1[3]);
                }
            }
        }
        fphase ^= 1;
    }

    // ---------------- fused epilogue ----------------
    const float cu  = 1.0f - (1.0f / 10.0f);
    const float au  = 1.0f / 10.0f;
    const float cv  = 1.0f - (1.0f / 150.0f);
    const float cvm = 10.0f / 150.0f;
    const size_t OUTV = (size_t)B_DIM * H_DIM;

#pragma unroll
    for (int mi = 0; mi < 4; mi++) {
#pragma unroll
        for (int ni = 0; ni < 4; ni++) {
            const int r0 = mb + wm * 64 + mi * 16 + lq;
            const int c  = nb + wn * 32 + ni * 8 + lr * 2;
            const float2 bn = *reinterpret_cast<const float2*>(bias + c);
#pragma unroll
            for (int h = 0; h < 2; h++) {
                const size_t off = (size_t)(r0 + 8 * h) * H_DIM + c;
                const float2 uu = *reinterpret_cast<const float2*>(u + off);
                const float2 vv = *reinterpret_cast<const float2*>(v + off);
                const float g0 = acc[mi][ni][2 * h + 0];
                const float g1 = acc[mi][ni][2 * h + 1];
                const float vn0 = fmaxf(cv * vv.x + cvm * uu.x, 0.0f);
                const float vn1 = fmaxf(cv * vv.y + cvm * uu.y, 0.0f);
                const float un0 = fmaxf(cu * uu.x + au * (g0 + bn.x - vn0), 0.0f);
                const float un1 = fmaxf(cu * uu.y + au * (g1 + bn.y - vn1), 0.0f);
                *reinterpret_cast<float2*>(out + off)        = make_float2(un0, un1);
                *reinterpret_cast<float2*>(out + OUTV + off) = make_float2(vn0, vn1);
            }
        }
    }
}

extern "C" void kernel_launch(void* const* d_in, const int* in_sizes, int n_in,
                              void* d_out, int out_size) {
    (void)in_sizes; (void)n_in; (void)out_size;
    const float* x    = (const float*)d_in[0];
    const float* u    = (const float*)d_in[1];
    const float* v    = (const float*)d_in[2];
    const float* win  = (const float*)d_in[3];
    const float* wr   = (const float*)d_in[4];
    const float* bias = (const float*)d_in[5];
    float* out = (float*)d_out;

    // 1) convert inputs to fp16 scratch
    const int cb = (int)(TOTAL4 / 256);  // 30720 blocks, exact
    convert_kernel<<<cb, 256>>>((const float4*)x, (const float4*)u,
                                (const float4*)win, (const float4*)wr);

    // 2) warp-specialized fused GEMM + epilogue
    cudaFuncSetAttribute(sfa_rnn_kernel,
                         cudaFuncAttributeMaxDynamicSharedMemorySize, SMEM_TOTAL);
    dim3 grid(H_DIM / BN, B_DIM / BM);  // (16, 64) = 1024 CTAs
    sfa_rnn_kernel<<<grid, NTHREADS, SMEM_TOTAL>>>(u, v, bias, out);
}